// round 9
// baseline (speedup 1.0000x reference)
#include <cuda_runtime.h>

#define NQ     12
#define TPB    512
#define NPARAM 240          // 12 * 4 * 5
#define NLAYER 4
#define FM     0xffffffffu

#define SMEM_BYTES 69856    // 2*32KB state bufs + trig + reduce buf

// new = A*v + B*p  (complex)
__device__ __forceinline__ float2 axpb(float2 A, float2 v, float2 B, float2 p) {
    return make_float2(
        fmaf(A.x, v.x, fmaf(-A.y, v.y, fmaf(B.x, p.x, -B.y * p.y))),
        fmaf(A.x, v.y, fmaf( A.y, v.x, fmaf(B.x, p.y,  B.y * p.x))));
}
// one-sided RX: n = c*v - i s*p
__device__ __forceinline__ float2 rx1(float2 v, float2 p, float c, float s) {
    return make_float2(fmaf(c, v.x, s * p.y), fmaf(c, v.y, -s * p.x));
}
// RX on a register pair
__device__ __forceinline__ void appRX(float2 &a, float2 &b, float c, float s) {
    float2 na = rx1(a, b, c, s);
    float2 nb = rx1(b, a, c, s);
    a = na; b = nb;
}
__device__ __forceinline__ float2 cmulf(float2 a, float2 b) {
    return make_float2(fmaf(a.x, b.x, -a.y * b.y), fmaf(a.x, b.y, a.y * b.x));
}
// M = Rz * Ry * Rx  (gates applied in order Rx, Ry, Rz)
__device__ __forceinline__ void build_u(const float* cs, const float* sn, int pi,
        float2 &M00, float2 &M01, float2 &M10, float2 &M11) {
    float cx = cs[pi],     sx = sn[pi];
    float cy = cs[pi + 1], sy = sn[pi + 1];
    float cz = cs[pi + 2], sz = sn[pi + 2];
    float2 A00 = make_float2( cy * cx,  sy * sx);
    float2 A01 = make_float2(-sy * cx, -cy * sx);
    float2 A10 = make_float2( sy * cx, -cy * sx);
    float2 A11 = make_float2( cy * cx, -sy * sx);
    float2 ez  = make_float2(cz, -sz), ezc = make_float2(cz, sz);
    M00 = cmulf(ez,  A00); M01 = cmulf(ez,  A01);
    M10 = cmulf(ezc, A10); M11 = cmulf(ezc, A11);
}
// M <- RX(c,s) * M   (RX applied after M)
__device__ __forceinline__ void fuse_rx(float c, float s,
        float2 &M00, float2 &M01, float2 &M10, float2 &M11) {
    float2 W00 = make_float2(fmaf(c, M00.x,  s * M10.y), fmaf(c, M00.y, -s * M10.x));
    float2 W01 = make_float2(fmaf(c, M01.x,  s * M11.y), fmaf(c, M01.y, -s * M11.x));
    float2 W10 = make_float2(fmaf(c, M10.x,  s * M00.y), fmaf(c, M10.y, -s * M00.x));
    float2 W11 = make_float2(fmaf(c, M11.x,  s * M01.y), fmaf(c, M11.y, -s * M01.x));
    M00 = W00; M01 = W01; M10 = W10; M11 = W11;
}

// State layout: idx = (k<<9) | t,  t in [0,512), k in [0,8).
// wire w <-> idx bit (11-w):
//   wires 0,1,2  <-> k bits 2,1,0       (register-local)
//   wires 3..6   <-> t bits 8..5        (smem exchange)
//   wires 7..11  <-> t bits 4..0        (shfl exchange)
__global__ void __launch_bounds__(TPB, 2) qfe_kernel(
    const float* __restrict__ params,   // (B, 240)
    const float* __restrict__ inputs,   // (B, 12)
    float* __restrict__ out)            // (B, 36)
{
    extern __shared__ float smem_raw[];
    float2* bufA = (float2*)smem_raw;           // 4096 float2 = 32 KB
    float2* bufB = bufA + 4096;                 // 32 KB
    float*  cs   = (float*)(bufB + 4096);       // 240
    float*  sn   = cs + NPARAM;                 // 240
    float*  eic  = sn + NPARAM;                 // 12
    float*  eis  = eic + NQ;                    // 12
    float*  rbuf = eis + NQ;                    // 576 = 36 outputs x 16 warps

    const int b = blockIdx.x;
    const int t = threadIdx.x;
    const int lane = t & 31, warp = t >> 5;

    // ---- stage all trig once per block
    if (t < NPARAM) {
        float h = 0.5f * params[b * NPARAM + t];
        sincosf(h, &sn[t], &cs[t]);
    } else if (t < NPARAM + NQ) {
        int i = t - NPARAM;
        float h = 0.5f * inputs[b * NQ + i];
        sincosf(h, &eis[i], &eic[i]);
    }
    __syncthreads();

    // ---- init: RY(input) product state
    float2 v[8];
    {
        float tp = 1.0f;
        #pragma unroll
        for (int w = 3; w < 12; w++)
            tp *= ((t >> (11 - w)) & 1) ? eis[w] : eic[w];
        #pragma unroll
        for (int k = 0; k < 8; k++) {
            float a = tp;
            #pragma unroll
            for (int w = 0; w < 3; w++)
                a *= ((k >> (2 - w)) & 1) ? eis[w] : eic[w];
            v[k] = make_float2(a, 0.0f);
        }
    }

    #pragma unroll 1
    for (int L = 0; L < NLAYER; L++) {
        const int base = 60 * L;

        // ===== U0..U2 on k bits (register-local) =====
        #pragma unroll
        for (int w = 0; w < 3; w++) {
            float2 M00, M01, M10, M11;
            build_u(cs, sn, base + 3 * w, M00, M01, M10, M11);
            int kb = 4 >> w;
            #pragma unroll
            for (int k = 0; k < 8; k++) if (!(k & kb)) {
                float2 s0 = v[k], s1 = v[k | kb];
                v[k]      = axpb(M00, s0, M01, s1);
                v[k | kb] = axpb(M11, s1, M10, s0);
            }
        }
        // ===== F0 (ctrl k2 -> tgt k1): k in {4,5} =====
        { float c = cs[base + 36], s = sn[base + 36];
          appRX(v[4], v[6], c, s); appRX(v[5], v[7], c, s); }
        // ===== F1 (ctrl k1 -> tgt k0): k in {2,6} =====
        { float c = cs[base + 37], s = sn[base + 37];
          appRX(v[2], v[3], c, s); appRX(v[6], v[7], c, s); }

        // ===== U3 + F2 (ctrl k0, per-k): smem axis t8 (xor 256) =====
        {
            float2 M00, M01, M10, M11;
            build_u(cs, sn, base + 9, M00, M01, M10, M11);
            float2 W00 = M00, W01 = M01, W10 = M10, W11 = M11;
            fuse_rx(cs[base + 38], sn[base + 38], W00, W01, W10, W11);
            int own = (t >> 8) & 1;
            float2 Am = own ? M11 : M00, Bm = own ? M10 : M01;
            float2 Aw = own ? W11 : W00, Bw = own ? W10 : W01;
            #pragma unroll
            for (int k = 0; k < 8; k++) bufA[(k << 9) | t] = v[k];
            __syncthreads();
            int pt = t ^ 256;
            #pragma unroll
            for (int k = 0; k < 8; k++) {
                float2 p = bufA[(k << 9) | pt];
                v[k] = (k & 1) ? axpb(Aw, v[k], Bw, p) : axpb(Am, v[k], Bm, p);
            }
        }
        // ===== U4 + F3 (cond t&256): smem axis t7 (xor 128) =====
        {
            float2 M00, M01, M10, M11;
            build_u(cs, sn, base + 12, M00, M01, M10, M11);
            if (t & 256) fuse_rx(cs[base + 39], sn[base + 39], M00, M01, M10, M11);
            int own = (t >> 7) & 1;
            float2 A = own ? M11 : M00, B = own ? M10 : M01;
            #pragma unroll
            for (int k = 0; k < 8; k++) bufB[(k << 9) | t] = v[k];
            __syncthreads();
            int pt = t ^ 128;
            #pragma unroll
            for (int k = 0; k < 8; k++)
                v[k] = axpb(A, v[k], B, bufB[(k << 9) | pt]);
        }
        // ===== U5 + F4 (cond t&128): smem axis t6 (xor 64) =====
        {
            float2 M00, M01, M10, M11;
            build_u(cs, sn, base + 15, M00, M01, M10, M11);
            if (t & 128) fuse_rx(cs[base + 40], sn[base + 40], M00, M01, M10, M11);
            int own = (t >> 6) & 1;
            float2 A = own ? M11 : M00, B = own ? M10 : M01;
            #pragma unroll
            for (int k = 0; k < 8; k++) bufA[(k << 9) | t] = v[k];
            __syncthreads();
            int pt = t ^ 64;
            #pragma unroll
            for (int k = 0; k < 8; k++)
                v[k] = axpb(A, v[k], B, bufA[(k << 9) | pt]);
        }
        // ===== U6 + F5 (cond t&64): smem axis t5 (xor 32) =====
        {
            float2 M00, M01, M10, M11;
            build_u(cs, sn, base + 18, M00, M01, M10, M11);
            if (t & 64) fuse_rx(cs[base + 41], sn[base + 41], M00, M01, M10, M11);
            int own = (t >> 5) & 1;
            float2 A = own ? M11 : M00, B = own ? M10 : M01;
            #pragma unroll
            for (int k = 0; k < 8; k++) bufB[(k << 9) | t] = v[k];
            __syncthreads();
            int pt = t ^ 32;
            #pragma unroll
            for (int k = 0; k < 8; k++)
                v[k] = axpb(A, v[k], B, bufB[(k << 9) | pt]);
        }
        // ===== U7..U11 + F6..F10 : shfl, axis m=1<<(11-w), cond t&(m<<1) =====
        #pragma unroll
        for (int w = 7; w < 12; w++) {
            const int m = 1 << (11 - w);
            float2 M00, M01, M10, M11;
            build_u(cs, sn, base + 3 * w, M00, M01, M10, M11);
            if (t & (m << 1))
                fuse_rx(cs[base + 36 + w - 1], sn[base + 36 + w - 1], M00, M01, M10, M11);
            int own = (t & m) ? 1 : 0;
            float2 A = own ? M11 : M00, B = own ? M10 : M01;
            #pragma unroll
            for (int k = 0; k < 8; k++) {
                float px = __shfl_xor_sync(FM, v[k].x, m);
                float py = __shfl_xor_sync(FM, v[k].y, m);
                v[k] = axpb(A, v[k], B, make_float2(px, py));
            }
        }
        // ===== F11: ctrl t0, tgt k2 (register-local) =====
        {
            float c = cs[base + 47], s = sn[base + 47];
            if (t & 1) {
                #pragma unroll
                for (int k = 0; k < 4; k++) appRX(v[k], v[k | 4], c, s);
            }
        }
        // ===== B11..B8: shfl CRX, tgt m, ctrl m>>1 =====
        #pragma unroll
        for (int i = 11; i >= 8; i--) {
            const int m = 1 << (12 - i);
            float c = cs[base + 48 + (11 - i)], s = sn[base + 48 + (11 - i)];
            int cond = t & (m >> 1);
            #pragma unroll
            for (int k = 0; k < 8; k++) {
                float px = __shfl_xor_sync(FM, v[k].x, m);
                float py = __shfl_xor_sync(FM, v[k].y, m);
                if (cond) v[k] = rx1(v[k], make_float2(px, py), c, s);
            }
        }
        // ===== B7: smem axis 32, cond t&16 =====
        {
            float c = cs[base + 52], s = sn[base + 52];
            int cond = t & 16;
            if (cond) {
                #pragma unroll
                for (int k = 0; k < 8; k++) bufA[(k << 9) | t] = v[k];
            }
            __syncthreads();
            if (cond) {
                int pt = t ^ 32;
                #pragma unroll
                for (int k = 0; k < 8; k++)
                    v[k] = rx1(v[k], bufA[(k << 9) | pt], c, s);
            }
        }
        // ===== B6: smem axis 64, cond t&32 =====
        {
            float c = cs[base + 53], s = sn[base + 53];
            int cond = t & 32;
            if (cond) {
                #pragma unroll
                for (int k = 0; k < 8; k++) bufB[(k << 9) | t] = v[k];
            }
            __syncthreads();
            if (cond) {
                int pt = t ^ 64;
                #pragma unroll
                for (int k = 0; k < 8; k++)
                    v[k] = rx1(v[k], bufB[(k << 9) | pt], c, s);
            }
        }
        // ===== B5: smem axis 128, cond t&64 =====
        {
            float c = cs[base + 54], s = sn[base + 54];
            int cond = t & 64;
            if (cond) {
                #pragma unroll
                for (int k = 0; k < 8; k++) bufA[(k << 9) | t] = v[k];
            }
            __syncthreads();
            if (cond) {
                int pt = t ^ 128;
                #pragma unroll
                for (int k = 0; k < 8; k++)
                    v[k] = rx1(v[k], bufA[(k << 9) | pt], c, s);
            }
        }
        // ===== B4: smem axis 256, cond t&128 =====
        {
            float c = cs[base + 55], s = sn[base + 55];
            int cond = t & 128;
            if (cond) {
                #pragma unroll
                for (int k = 0; k < 8; k++) bufB[(k << 9) | t] = v[k];
            }
            __syncthreads();
            if (cond) {
                int pt = t ^ 256;
                #pragma unroll
                for (int k = 0; k < 8; k++)
                    v[k] = rx1(v[k], bufB[(k << 9) | pt], c, s);
            }
        }
        // ===== B3: ctrl t8, tgt k0 (register-local) =====
        {
            float c = cs[base + 56], s = sn[base + 56];
            if (t & 256) {
                #pragma unroll
                for (int k = 0; k < 8; k += 2) appRX(v[k], v[k | 1], c, s);
            }
        }
        // ===== B2 (ctrl k0 -> tgt k1): k in {1,5} =====
        { float c = cs[base + 57], s = sn[base + 57];
          appRX(v[1], v[3], c, s); appRX(v[5], v[7], c, s); }
        // ===== B1 (ctrl k1 -> tgt k2): k in {2,3} =====
        { float c = cs[base + 58], s = sn[base + 58];
          appRX(v[2], v[6], c, s); appRX(v[3], v[7], c, s); }
        // ===== B0: ctrl k2, tgt t0 (shfl m=1, k>=4 only) =====
        {
            float c = cs[base + 59], s = sn[base + 59];
            #pragma unroll
            for (int k = 4; k < 8; k++) {
                float px = __shfl_xor_sync(FM, v[k].x, 1);
                float py = __shfl_xor_sync(FM, v[k].y, 1);
                v[k] = rx1(v[k], make_float2(px, py), c, s);
            }
        }
    }

    // ================= expectations =================
    #pragma unroll
    for (int k = 0; k < 8; k++) bufA[(k << 9) | t] = v[k];
    __syncthreads();

    float nv[8], S = 0.0f;
    #pragma unroll
    for (int k = 0; k < 8; k++) {
        nv[k] = fmaf(v[k].x, v[k].x, v[k].y * v[k].y);
        S += nv[k];
    }

    // wires 0-2: k-bit pairs (register-local)
    #pragma unroll
    for (int w = 0; w < 3; w++) {
        int kb = 4 >> w;
        float rr = 0.f, ri = 0.f, rz = 0.f;
        #pragma unroll
        for (int k = 0; k < 8; k++) {
            if (!(k & kb)) {
                float2 a = v[k], c = v[k | kb];
                rr = fmaf(a.x, c.x, fmaf( a.y, c.y, rr));
                ri = fmaf(a.x, c.y, fmaf(-a.y, c.x, ri));
            }
            rz += (k & kb) ? -nv[k] : nv[k];
        }
        #pragma unroll
        for (int off = 16; off; off >>= 1) {
            rr += __shfl_down_sync(FM, rr, off);
            ri += __shfl_down_sync(FM, ri, off);
            rz += __shfl_down_sync(FM, rz, off);
        }
        if (lane == 0) {
            rbuf[w * 16 + warp]          = rr;
            rbuf[(12 + w) * 16 + warp]   = ri;
            rbuf[(24 + w) * 16 + warp]   = rz;
        }
    }

    // wires 3-6: warp-bit pairs (partner from bufA; own-bit==0 threads only)
    #pragma unroll
    for (int w = 3; w < 7; w++) {
        int pb = 11 - w;
        int own = (t >> pb) & 1;
        float rr = 0.f, ri = 0.f;
        if (!own) {
            int pt = t | (1 << pb);
            #pragma unroll
            for (int k = 0; k < 8; k++) {
                float2 c = bufA[(k << 9) | pt];
                rr = fmaf(v[k].x, c.x, fmaf( v[k].y, c.y, rr));
                ri = fmaf(v[k].x, c.y, fmaf(-v[k].y, c.x, ri));
            }
        }
        float rz = own ? -S : S;
        #pragma unroll
        for (int off = 16; off; off >>= 1) {
            rr += __shfl_down_sync(FM, rr, off);
            ri += __shfl_down_sync(FM, ri, off);
            rz += __shfl_down_sync(FM, rz, off);
        }
        if (lane == 0) {
            rbuf[w * 16 + warp]          = rr;
            rbuf[(12 + w) * 16 + warp]   = ri;
            rbuf[(24 + w) * 16 + warp]   = rz;
        }
    }

    // wires 7-11: lane-bit pairs (shfl partner)
    #pragma unroll
    for (int w = 7; w < 12; w++) {
        int m = 1 << (11 - w);
        int own = (t & m) ? 1 : 0;
        float rr = 0.f, ri = 0.f;
        #pragma unroll
        for (int k = 0; k < 8; k++) {
            float px = __shfl_xor_sync(FM, v[k].x, m);
            float py = __shfl_xor_sync(FM, v[k].y, m);
            if (!own) {
                rr = fmaf(v[k].x, px, fmaf( v[k].y, py, rr));
                ri = fmaf(v[k].x, py, fmaf(-v[k].y, px, ri));
            }
        }
        float rz = own ? -S : S;
        #pragma unroll
        for (int off = 16; off; off >>= 1) {
            rr += __shfl_down_sync(FM, rr, off);
            ri += __shfl_down_sync(FM, ri, off);
            rz += __shfl_down_sync(FM, rz, off);
        }
        if (lane == 0) {
            rbuf[w * 16 + warp]          = rr;
            rbuf[(12 + w) * 16 + warp]   = ri;
            rbuf[(24 + w) * 16 + warp]   = rz;
        }
    }

    __syncthreads();
    if (t < 36) {
        float a = 0.f;
        #pragma unroll
        for (int q = 0; q < 16; q++) a += rbuf[t * 16 + q];
        out[b * 36 + t] = (t < 24) ? 2.0f * a : a;
    }
}

extern "C" void kernel_launch(void* const* d_in, const int* in_sizes, int n_in,
                              void* d_out, int out_size) {
    const float* params = (const float*)d_in[0];   // (B, 240) float32
    const float* inputs = (const float*)d_in[1];   // (B, 12)  float32
    float* out = (float*)d_out;                    // (B, 36)  float32
    int B = in_sizes[0] / NPARAM;
    static bool attr_set = false;
    if (!attr_set) {
        cudaFuncSetAttribute(qfe_kernel,
                             cudaFuncAttributeMaxDynamicSharedMemorySize,
                             SMEM_BYTES);
        attr_set = true;
    }
    qfe_kernel<<<B, TPB, SMEM_BYTES>>>(params, inputs, out);
}

// round 11
// speedup vs baseline: 1.3202x; 1.3202x over previous
#include <cuda_runtime.h>

#define NQ     12
#define TPB    256
#define NPARAM 240          // 12 * 4 * 5
#define NLAYER 4
#define FM     0xffffffffu

#define SMEM_BYTES 68704

// new = A*v + B*p  (complex)
__device__ __forceinline__ float2 axpb(float2 A, float2 v, float2 B, float2 p) {
    return make_float2(
        fmaf(A.x, v.x, fmaf(-A.y, v.y, fmaf(B.x, p.x, -B.y * p.y))),
        fmaf(A.x, v.y, fmaf( A.y, v.x, fmaf(B.x, p.y,  B.y * p.x))));
}
// one-sided RX: n = c*v - i s*p
__device__ __forceinline__ float2 rx1(float2 v, float2 p, float c, float s) {
    return make_float2(fmaf(c, v.x, s * p.y), fmaf(c, v.y, -s * p.x));
}
// RX on a register pair
__device__ __forceinline__ void appRX(float2 &a, float2 &b, float c, float s) {
    float2 na = rx1(a, b, c, s);
    float2 nb = rx1(b, a, c, s);
    a = na; b = nb;
}
__device__ __forceinline__ float2 cmulf(float2 a, float2 b) {
    return make_float2(fmaf(a.x, b.x, -a.y * b.y), fmaf(a.x, b.y, a.y * b.x));
}
// M = Rz * Ry * Rx  (gates applied in order Rx, Ry, Rz)
__device__ __forceinline__ void build_u(const float* cs, const float* sn, int pi,
        float2 &M00, float2 &M01, float2 &M10, float2 &M11) {
    float cx = cs[pi],     sx = sn[pi];
    float cy = cs[pi + 1], sy = sn[pi + 1];
    float cz = cs[pi + 2], sz = sn[pi + 2];
    float2 A00 = make_float2( cy * cx,  sy * sx);
    float2 A01 = make_float2(-sy * cx, -cy * sx);
    float2 A10 = make_float2( sy * cx, -cy * sx);
    float2 A11 = make_float2( cy * cx, -sy * sx);
    float2 ez  = make_float2(cz, -sz), ezc = make_float2(cz, sz);
    M00 = cmulf(ez,  A00); M01 = cmulf(ez,  A01);
    M10 = cmulf(ezc, A10); M11 = cmulf(ezc, A11);
}
// M <- RX(c,s) * M   (RX applied after M)
__device__ __forceinline__ void fuse_rx(float c, float s,
        float2 &M00, float2 &M01, float2 &M10, float2 &M11) {
    float2 W00 = make_float2(fmaf(c, M00.x,  s * M10.y), fmaf(c, M00.y, -s * M10.x));
    float2 W01 = make_float2(fmaf(c, M01.x,  s * M11.y), fmaf(c, M01.y, -s * M11.x));
    float2 W10 = make_float2(fmaf(c, M10.x,  s * M00.y), fmaf(c, M10.y, -s * M00.x));
    float2 W11 = make_float2(fmaf(c, M11.x,  s * M01.y), fmaf(c, M11.y, -s * M01.x));
    M00 = W00; M01 = W01; M10 = W10; M11 = W11;
}

// Mappings (idx bit 11-w <-> wire w physically; mapping = which storage slot):
//  M0: slot(k,t): i = (k<<8)|t.     wires 0-3 <-> k3..k0 ; wires 4-6 <-> t7..t5 ; 7-11 <-> t4..t0
//  M1: slot(k,t): i11=k3, i10..i8 = t7..t5, i7..i5 = k2..k0, i4..i0 = t4..t0
//      wires 0,4,5,6 <-> k3,k2,k1,k0 ; wires 1,2,3 <-> t7,t6,t5 ; 7-11 <-> t4..t0
__global__ void __launch_bounds__(TPB, 2) qfe_kernel(
    const float* __restrict__ params,   // (B, 240)
    const float* __restrict__ inputs,   // (B, 12)
    float* __restrict__ out)            // (B, 36)
{
    extern __shared__ float smem_raw[];
    float2* bufA = (float2*)smem_raw;           // 4096 float2 = 32 KB
    float2* bufB = bufA + 4096;                 // 32 KB
    float*  cs   = (float*)(bufB + 4096);       // 240
    float*  sn   = cs + NPARAM;                 // 240
    float*  eic  = sn + NPARAM;                 // 12
    float*  eis  = eic + NQ;                    // 12
    float*  rbuf = eis + NQ;                    // 288

    const int b = blockIdx.x;
    const int t = threadIdx.x;
    const int lane = t & 31, warp = t >> 5;
    // M1 address base for this thread: bits 10-8 <- t7..t5, bits 4-0 <- t4..t0
    const int tbase = ((t & 0xE0) << 3) | (t & 31);

    // ---- stage all trig once per block
    if (t < NPARAM) {
        float h = 0.5f * params[b * NPARAM + t];
        sincosf(h, &sn[t], &cs[t]);
    } else if (t < NPARAM + NQ) {
        int i = t - NPARAM;
        float h = 0.5f * inputs[b * NQ + i];
        sincosf(h, &eis[i], &eic[i]);
    }
    __syncthreads();

    // ---- init (M0): RY(input) product state
    float2 v[16];
    {
        float tp = 1.0f;
        #pragma unroll
        for (int w = 4; w < 12; w++)
            tp *= ((t >> (11 - w)) & 1) ? eis[w] : eic[w];
        #pragma unroll
        for (int k = 0; k < 16; k++) {
            float a = tp;
            #pragma unroll
            for (int w = 0; w < 4; w++)
                a *= ((k >> (3 - w)) & 1) ? eis[w] : eic[w];
            v[k] = make_float2(a, 0.0f);
        }
    }

    #pragma unroll 1
    for (int L = 0; L < NLAYER; L++) {
        const int base = 60 * L;

        // ========== Phase 1 (M0): U0..U3, F0..F2 — all register-local ==========
        #pragma unroll
        for (int w = 0; w < 4; w++) {
            float2 M00, M01, M10, M11;
            build_u(cs, sn, base + 3 * w, M00, M01, M10, M11);
            int kb = 8 >> w;
            #pragma unroll
            for (int k = 0; k < 16; k++) if (!(k & kb)) {
                float2 s0 = v[k], s1 = v[k | kb];
                v[k]      = axpb(M00, s0, M01, s1);
                v[k | kb] = axpb(M11, s1, M10, s0);
            }
        }
        #pragma unroll
        for (int i = 0; i < 3; i++) {    // F0,F1,F2: ctrl k(3-i) -> tgt k(2-i)
            float c = cs[base + 36 + i], s = sn[base + 36 + i];
            int cb = 8 >> i, tb = 4 >> i;
            #pragma unroll
            for (int k = 0; k < 16; k++)
                if ((k & cb) && !(k & tb)) appRX(v[k], v[k | tb], c, s);
        }

        // ========== Transpose M0 -> M1 (bufA) ==========
        #pragma unroll
        for (int k = 0; k < 16; k++) bufA[(k << 8) | t] = v[k];
        __syncthreads();
        #pragma unroll
        for (int k = 0; k < 16; k++)
            v[k] = bufA[tbase | ((k & 8) << 8) | ((k & 7) << 5)];

        // ========== Phase 2 (M1) ==========
        // U4,U5,U6: k-local (k2,k1,k0)
        #pragma unroll
        for (int j = 0; j < 3; j++) {
            float2 M00, M01, M10, M11;
            build_u(cs, sn, base + 12 + 3 * j, M00, M01, M10, M11);
            int kb = 4 >> j;
            #pragma unroll
            for (int k = 0; k < 16; k++) if (!(k & kb)) {
                float2 s0 = v[k], s1 = v[k | kb];
                v[k]      = axpb(M00, s0, M01, s1);
                v[k | kb] = axpb(M11, s1, M10, s0);
            }
        }
        // F3: ctrl wire3=t5 (t&32), tgt wire4=k2
        {
            float c = cs[base + 39], s = sn[base + 39];
            if (t & 32) {
                #pragma unroll
                for (int k = 0; k < 16; k++)
                    if (!(k & 4)) appRX(v[k], v[k | 4], c, s);
            }
        }
        // F4: ctrl k2 -> tgt k1 ; F5: ctrl k1 -> tgt k0
        {
            float c = cs[base + 40], s = sn[base + 40];
            #pragma unroll
            for (int k = 0; k < 16; k++)
                if ((k & 4) && !(k & 2)) appRX(v[k], v[k | 2], c, s);
        }
        {
            float c = cs[base + 41], s = sn[base + 41];
            #pragma unroll
            for (int k = 0; k < 16; k++)
                if ((k & 2) && !(k & 1)) appRX(v[k], v[k | 1], c, s);
        }
        // U7 + F6 (ctrl wire6=k0, per-k select): shfl m=16
        {
            float2 M00, M01, M10, M11;
            build_u(cs, sn, base + 21, M00, M01, M10, M11);
            float2 W00 = M00, W01 = M01, W10 = M10, W11 = M11;
            fuse_rx(cs[base + 42], sn[base + 42], W00, W01, W10, W11);
            int own = (t >> 4) & 1;
            float2 Am = own ? M11 : M00, Bm = own ? M10 : M01;
            float2 Aw = own ? W11 : W00, Bw = own ? W10 : W01;
            #pragma unroll
            for (int k = 0; k < 16; k++) {
                float px = __shfl_xor_sync(FM, v[k].x, 16);
                float py = __shfl_xor_sync(FM, v[k].y, 16);
                float2 p = make_float2(px, py);
                v[k] = (k & 1) ? axpb(Aw, v[k], Bw, p) : axpb(Am, v[k], Bm, p);
            }
        }
        // U8..U11 + F7..F10: shfl m=8,4,2,1 ; ctrl bit = m<<1
        #pragma unroll
        for (int w = 8; w < 12; w++) {
            const int m = 1 << (11 - w);
            float2 M00, M01, M10, M11;
            build_u(cs, sn, base + 3 * w, M00, M01, M10, M11);
            if (t & (m << 1))
                fuse_rx(cs[base + 36 + w - 1], sn[base + 36 + w - 1], M00, M01, M10, M11);
            int own = (t & m) ? 1 : 0;
            float2 A = own ? M11 : M00, B = own ? M10 : M01;
            #pragma unroll
            for (int k = 0; k < 16; k++) {
                float px = __shfl_xor_sync(FM, v[k].x, m);
                float py = __shfl_xor_sync(FM, v[k].y, m);
                v[k] = axpb(A, v[k], B, make_float2(px, py));
            }
        }
        // F11: ctrl wire11=t0, tgt wire0=k3 (local)
        {
            float c = cs[base + 47], s = sn[base + 47];
            if (t & 1) {
                #pragma unroll
                for (int k = 0; k < 8; k++) appRX(v[k], v[k | 8], c, s);
            }
        }
        // B11..B8: shfl CRX, tgt m=2,4,8,16 ; ctrl = m>>1
        #pragma unroll
        for (int i = 11; i >= 8; i--) {
            const int m = 1 << (12 - i);
            float c = cs[base + 48 + (11 - i)], s = sn[base + 48 + (11 - i)];
            int cond = t & (m >> 1);
            #pragma unroll
            for (int k = 0; k < 16; k++) {
                float px = __shfl_xor_sync(FM, v[k].x, m);
                float py = __shfl_xor_sync(FM, v[k].y, m);
                if (cond) v[k] = rx1(v[k], make_float2(px, py), c, s);
            }
        }
        // B7: ctrl wire7=t4 (t&16), tgt wire6=k0 (local)
        {
            float c = cs[base + 52], s = sn[base + 52];
            if (t & 16) {
                #pragma unroll
                for (int k = 0; k < 16; k += 2) appRX(v[k], v[k | 1], c, s);
            }
        }
        // B6: ctrl k0 -> tgt k1 ; B5: ctrl k1 -> tgt k2 (local)
        {
            float c = cs[base + 53], s = sn[base + 53];
            #pragma unroll
            for (int k = 0; k < 16; k++)
                if ((k & 1) && !(k & 2)) appRX(v[k], v[k | 2], c, s);
        }
        {
            float c = cs[base + 54], s = sn[base + 54];
            #pragma unroll
            for (int k = 0; k < 16; k++)
                if ((k & 2) && !(k & 4)) appRX(v[k], v[k | 4], c, s);
        }

        // ========== Transpose M1 -> M0 (bufB) ==========
        #pragma unroll
        for (int k = 0; k < 16; k++)
            bufB[tbase | ((k & 8) << 8) | ((k & 7) << 5)] = v[k];
        __syncthreads();
        #pragma unroll
        for (int k = 0; k < 16; k++) v[k] = bufB[(k << 8) | t];

        // ========== Phase 3 (M0): B4..B0 ==========
        // B4: ctrl wire4=t7 (t&128), tgt wire3=k0
        {
            float c = cs[base + 55], s = sn[base + 55];
            if (t & 128) {
                #pragma unroll
                for (int k = 0; k < 16; k += 2) appRX(v[k], v[k | 1], c, s);
            }
        }
        // B3,B2,B1: ctrl k(j) -> tgt k(j+1)
        #pragma unroll
        for (int j = 0; j < 3; j++) {
            float c = cs[base + 56 + j], s = sn[base + 56 + j];
            int cb = 1 << j, tb = 2 << j;
            #pragma unroll
            for (int k = 0; k < 16; k++)
                if ((k & cb) && !(k & tb)) appRX(v[k], v[k | tb], c, s);
        }
        // B0: ctrl wire0=k3 (k>=8), tgt wire11=t0 (shfl m=1)
        {
            float c = cs[base + 59], s = sn[base + 59];
            #pragma unroll
            for (int k = 8; k < 16; k++) {
                float px = __shfl_xor_sync(FM, v[k].x, 1);
                float py = __shfl_xor_sync(FM, v[k].y, 1);
                v[k] = rx1(v[k], make_float2(px, py), c, s);
            }
        }
    }

    // ================= expectations (M0) =================
    #pragma unroll
    for (int k = 0; k < 16; k++) bufA[(k << 8) | t] = v[k];
    __syncthreads();

    float nv[16], S = 0.0f;
    #pragma unroll
    for (int k = 0; k < 16; k++) {
        nv[k] = fmaf(v[k].x, v[k].x, v[k].y * v[k].y);
        S += nv[k];
    }

    // wires 0-3: k-bit pairs (register-local)
    #pragma unroll
    for (int w = 0; w < 4; w++) {
        int kb = 1 << (3 - w);
        float rr = 0.f, ri = 0.f, rz = 0.f;
        #pragma unroll
        for (int k = 0; k < 16; k++) {
            if (!(k & kb)) {
                float2 a = v[k], c = v[k | kb];
                rr = fmaf(a.x, c.x, fmaf( a.y, c.y, rr));
                ri = fmaf(a.x, c.y, fmaf(-a.y, c.x, ri));
            }
            rz += (k & kb) ? -nv[k] : nv[k];
        }
        #pragma unroll
        for (int off = 16; off; off >>= 1) {
            rr += __shfl_down_sync(FM, rr, off);
            ri += __shfl_down_sync(FM, ri, off);
            rz += __shfl_down_sync(FM, rz, off);
        }
        if (lane == 0) {
            rbuf[w * 8 + warp]       = rr;
            rbuf[96 + w * 8 + warp]  = ri;
            rbuf[192 + w * 8 + warp] = rz;
        }
    }

    // wires 4-6: warp-bit pairs (partner from bufA; own-bit==0 threads only)
    #pragma unroll
    for (int w = 4; w < 7; w++) {
        int pb = 11 - w;
        int own = (t >> pb) & 1;
        float rr = 0.f, ri = 0.f;
        if (!own) {
            int pt = t | (1 << pb);
            #pragma unroll
            for (int k = 0; k < 16; k++) {
                float2 c = bufA[(k << 8) | pt];
                rr = fmaf(v[k].x, c.x, fmaf( v[k].y, c.y, rr));
                ri = fmaf(v[k].x, c.y, fmaf(-v[k].y, c.x, ri));
            }
        }
        float rz = own ? -S : S;
        #pragma unroll
        for (int off = 16; off; off >>= 1) {
            rr += __shfl_down_sync(FM, rr, off);
            ri += __shfl_down_sync(FM, ri, off);
            rz += __shfl_down_sync(FM, rz, off);
        }
        if (lane == 0) {
            rbuf[w * 8 + warp]       = rr;
            rbuf[96 + w * 8 + warp]  = ri;
            rbuf[192 + w * 8 + warp] = rz;
        }
    }

    // wires 7-11: lane-bit pairs (shfl partner)
    #pragma unroll
    for (int w = 7; w < 12; w++) {
        int m = 1 << (11 - w);
        int own = (t & m) ? 1 : 0;
        float rr = 0.f, ri = 0.f;
        #pragma unroll
        for (int k = 0; k < 16; k++) {
            float px = __shfl_xor_sync(FM, v[k].x, m);
            float py = __shfl_xor_sync(FM, v[k].y, m);
            if (!own) {
                rr = fmaf(v[k].x, px, fmaf( v[k].y, py, rr));
                ri = fmaf(v[k].x, py, fmaf(-v[k].y, px, ri));
            }
        }
        float rz = own ? -S : S;
        #pragma unroll
        for (int off = 16; off; off >>= 1) {
            rr += __shfl_down_sync(FM, rr, off);
            ri += __shfl_down_sync(FM, ri, off);
            rz += __shfl_down_sync(FM, rz, off);
        }
        if (lane == 0) {
            rbuf[w * 8 + warp]       = rr;
            rbuf[96 + w * 8 + warp]  = ri;
            rbuf[192 + w * 8 + warp] = rz;
        }
    }

    __syncthreads();
    if (t < 36) {
        float a = 0.f;
        #pragma unroll
        for (int q = 0; q < 8; q++) a += rbuf[t * 8 + q];
        out[b * 36 + t] = (t < 24) ? 2.0f * a : a;
    }
}

extern "C" void kernel_launch(void* const* d_in, const int* in_sizes, int n_in,
                              void* d_out, int out_size) {
    const float* params = (const float*)d_in[0];   // (B, 240) float32
    const float* inputs = (const float*)d_in[1];   // (B, 12)  float32
    float* out = (float*)d_out;                    // (B, 36)  float32
    int B = in_sizes[0] / NPARAM;
    static bool attr_set = false;
    if (!attr_set) {
        cudaFuncSetAttribute(qfe_kernel,
                             cudaFuncAttributeMaxDynamicSharedMemorySize,
                             SMEM_BYTES);
        attr_set = true;
    }
    qfe_kernel<<<B, TPB, SMEM_BYTES>>>(params, inputs, out);
}

// round 12
// speedup vs baseline: 1.4080x; 1.0665x over previous
#include <cuda_runtime.h>

#define NQ     12
#define TPB    256
#define NPARAM 240          // 12 * 4 * 5
#define NLAYER 4
#define FM     0xffffffffu

// 64KB state bufs + 8704B matrices + trig/reduce floats
#define SMEM_BYTES 77408

// new = A*v + B*p  (complex)
__device__ __forceinline__ float2 axpb(float2 A, float2 v, float2 B, float2 p) {
    return make_float2(
        fmaf(A.x, v.x, fmaf(-A.y, v.y, fmaf(B.x, p.x, -B.y * p.y))),
        fmaf(A.x, v.y, fmaf( A.y, v.x, fmaf(B.x, p.y,  B.y * p.x))));
}
// one-sided RX: n = c*v - i s*p
__device__ __forceinline__ float2 rx1(float2 v, float2 p, float c, float s) {
    return make_float2(fmaf(c, v.x, s * p.y), fmaf(c, v.y, -s * p.x));
}
// RX on a register pair
__device__ __forceinline__ void appRX(float2 &a, float2 &b, float c, float s) {
    float2 na = rx1(a, b, c, s);
    float2 nb = rx1(b, a, c, s);
    a = na; b = nb;
}
__device__ __forceinline__ float2 cmulf(float2 a, float2 b) {
    return make_float2(fmaf(a.x, b.x, -a.y * b.y), fmaf(a.x, b.y, a.y * b.x));
}
// M = Rz * Ry * Rx  (gates applied in order Rx, Ry, Rz)
__device__ __forceinline__ void build_u(const float* cs, const float* sn, int pi,
        float2 &M00, float2 &M01, float2 &M10, float2 &M11) {
    float cx = cs[pi],     sx = sn[pi];
    float cy = cs[pi + 1], sy = sn[pi + 1];
    float cz = cs[pi + 2], sz = sn[pi + 2];
    float2 A00 = make_float2( cy * cx,  sy * sx);
    float2 A01 = make_float2(-sy * cx, -cy * sx);
    float2 A10 = make_float2( sy * cx, -cy * sx);
    float2 A11 = make_float2( cy * cx, -sy * sx);
    float2 ez  = make_float2(cz, -sz), ezc = make_float2(cz, sz);
    M00 = cmulf(ez,  A00); M01 = cmulf(ez,  A01);
    M10 = cmulf(ezc, A10); M11 = cmulf(ezc, A11);
}
// M <- RX(c,s) * M   (RX applied after M)
__device__ __forceinline__ void fuse_rx(float c, float s,
        float2 &M00, float2 &M01, float2 &M10, float2 &M11) {
    float2 W00 = make_float2(fmaf(c, M00.x,  s * M10.y), fmaf(c, M00.y, -s * M10.x));
    float2 W01 = make_float2(fmaf(c, M01.x,  s * M11.y), fmaf(c, M01.y, -s * M11.x));
    float2 W10 = make_float2(fmaf(c, M10.x,  s * M00.y), fmaf(c, M10.y, -s * M00.x));
    float2 W11 = make_float2(fmaf(c, M11.x,  s * M01.y), fmaf(c, M11.y, -s * M01.x));
    M00 = W00; M01 = W01; M10 = W10; M11 = W11;
}

// Precomputed matrix table: 17 slots per layer, 2 float4 per slot.
//  slots 0-3 : U0..U3   full layout  [M00,M01],[M10,M11]
//  slots 4-6 : U4..U6   full layout
//  slot  7   : U7       pair layout  [M00|M11],[M01|M10]
//  slot  8   : W7=F6*U7 pair layout
//  slots 9-12: U8..U11  pair layout
//  slots13-16: W8..W11  pair layout (F_{w-1} fused)
//
// Mappings (idx bit 11-w <-> wire w physically):
//  M0: i = (k<<8)|t.  wires 0-3 <-> k3..k0 ; 4-6 <-> t7..t5 ; 7-11 <-> t4..t0
//  M1: i11=k3, i10..i8=t7..t5, i7..i5=k2..k0, i4..i0=t4..t0
__global__ void __launch_bounds__(TPB, 2) qfe_kernel(
    const float* __restrict__ params,   // (B, 240)
    const float* __restrict__ inputs,   // (B, 12)
    float* __restrict__ out)            // (B, 36)
{
    extern __shared__ float smem_raw[];
    float2* bufA = (float2*)smem_raw;            // 4096 float2 = 32 KB
    float2* bufB = bufA + 4096;                  // 32 KB
    float4* gmat = (float4*)(bufB + 4096);       // 544 float4 = 8704 B
    float*  cs   = (float*)(gmat + 544);         // 240
    float*  sn   = cs + NPARAM;                  // 240
    float*  eic  = sn + NPARAM;                  // 12
    float*  eis  = eic + NQ;                     // 12
    float*  rbuf = eis + NQ;                     // 288

    const int b = blockIdx.x;
    const int t = threadIdx.x;
    const int lane = t & 31, warp = t >> 5;
    // M1 address base: bits 10-8 <- t7..t5, bits 4-0 <- t4..t0
    const int tbase = ((t & 0xE0) << 3) | (t & 31);

    // ---- stage all trig once per block
    if (t < NPARAM) {
        float h = 0.5f * params[b * NPARAM + t];
        sincosf(h, &sn[t], &cs[t]);
    } else if (t < NPARAM + NQ) {
        int i = t - NPARAM;
        float h = 0.5f * inputs[b * NQ + i];
        sincosf(h, &eis[i], &eic[i]);
    }
    __syncthreads();

    // ---- build all gate matrices once per block (68 builder threads)
    if (t < 68) {
        int L = t / 17, slot = t - L * 17;
        int base = 60 * L;
        float2 M00, M01, M10, M11;
        int full;
        if (slot < 4) {          // U0..U3
            build_u(cs, sn, base + 3 * slot, M00, M01, M10, M11); full = 1;
        } else if (slot < 7) {   // U4..U6
            build_u(cs, sn, base + 12 + 3 * (slot - 4), M00, M01, M10, M11); full = 1;
        } else if (slot == 7) {  // U7
            build_u(cs, sn, base + 21, M00, M01, M10, M11); full = 0;
        } else if (slot == 8) {  // W7 = F6 * U7
            build_u(cs, sn, base + 21, M00, M01, M10, M11);
            fuse_rx(cs[base + 42], sn[base + 42], M00, M01, M10, M11); full = 0;
        } else if (slot < 13) {  // U8..U11
            int w = slot - 9 + 8;
            build_u(cs, sn, base + 3 * w, M00, M01, M10, M11); full = 0;
        } else {                 // W8..W11 = F_{w-1} * U_w
            int w = slot - 13 + 8;
            build_u(cs, sn, base + 3 * w, M00, M01, M10, M11);
            fuse_rx(cs[base + 36 + w - 1], sn[base + 36 + w - 1], M00, M01, M10, M11);
            full = 0;
        }
        float4 r0, r1;
        if (full) {
            r0 = make_float4(M00.x, M00.y, M01.x, M01.y);
            r1 = make_float4(M10.x, M10.y, M11.x, M11.y);
        } else {   // pair layout for own-bit select
            r0 = make_float4(M00.x, M00.y, M11.x, M11.y);
            r1 = make_float4(M01.x, M01.y, M10.x, M10.y);
        }
        gmat[(L * 17 + slot) * 2 + 0] = r0;
        gmat[(L * 17 + slot) * 2 + 1] = r1;
    }

    // ---- init (M0): RY(input) product state (overlap with builder, sync after)
    float2 v[16];
    {
        float tp = 1.0f;
        #pragma unroll
        for (int w = 4; w < 12; w++)
            tp *= ((t >> (11 - w)) & 1) ? eis[w] : eic[w];
        #pragma unroll
        for (int k = 0; k < 16; k++) {
            float a = tp;
            #pragma unroll
            for (int w = 0; w < 4; w++)
                a *= ((k >> (3 - w)) & 1) ? eis[w] : eic[w];
            v[k] = make_float2(a, 0.0f);
        }
    }
    __syncthreads();

    #pragma unroll 1
    for (int L = 0; L < NLAYER; L++) {
        const int base = 60 * L;
        const float4* gL = gmat + L * 34;

        // ========== Phase 1 (M0): U0..U3, F0..F2 — register-local ==========
        #pragma unroll
        for (int w = 0; w < 4; w++) {
            float4 r0 = gL[2 * w], r1 = gL[2 * w + 1];
            float2 M00 = make_float2(r0.x, r0.y), M01 = make_float2(r0.z, r0.w);
            float2 M10 = make_float2(r1.x, r1.y), M11 = make_float2(r1.z, r1.w);
            int kb = 8 >> w;
            #pragma unroll
            for (int k = 0; k < 16; k++) if (!(k & kb)) {
                float2 s0 = v[k], s1 = v[k | kb];
                v[k]      = axpb(M00, s0, M01, s1);
                v[k | kb] = axpb(M11, s1, M10, s0);
            }
        }
        #pragma unroll
        for (int i = 0; i < 3; i++) {    // F0,F1,F2: ctrl k(3-i) -> tgt k(2-i)
            float c = cs[base + 36 + i], s = sn[base + 36 + i];
            int cb = 8 >> i, tb = 4 >> i;
            #pragma unroll
            for (int k = 0; k < 16; k++)
                if ((k & cb) && !(k & tb)) appRX(v[k], v[k | tb], c, s);
        }

        // ========== Transpose M0 -> M1 (bufA) ==========
        #pragma unroll
        for (int k = 0; k < 16; k++) bufA[(k << 8) | t] = v[k];
        __syncthreads();
        #pragma unroll
        for (int k = 0; k < 16; k++)
            v[k] = bufA[tbase | ((k & 8) << 8) | ((k & 7) << 5)];

        // ========== Phase 2 (M1) ==========
        // U4,U5,U6: k-local (k2,k1,k0)
        #pragma unroll
        for (int j = 0; j < 3; j++) {
            float4 r0 = gL[2 * (4 + j)], r1 = gL[2 * (4 + j) + 1];
            float2 M00 = make_float2(r0.x, r0.y), M01 = make_float2(r0.z, r0.w);
            float2 M10 = make_float2(r1.x, r1.y), M11 = make_float2(r1.z, r1.w);
            int kb = 4 >> j;
            #pragma unroll
            for (int k = 0; k < 16; k++) if (!(k & kb)) {
                float2 s0 = v[k], s1 = v[k | kb];
                v[k]      = axpb(M00, s0, M01, s1);
                v[k | kb] = axpb(M11, s1, M10, s0);
            }
        }
        // F3: ctrl wire3=t5 (t&32), tgt wire4=k2
        {
            float c = cs[base + 39], s = sn[base + 39];
            if (t & 32) {
                #pragma unroll
                for (int k = 0; k < 16; k++)
                    if (!(k & 4)) appRX(v[k], v[k | 4], c, s);
            }
        }
        // F4: ctrl k2 -> tgt k1 ; F5: ctrl k1 -> tgt k0
        {
            float c = cs[base + 40], s = sn[base + 40];
            #pragma unroll
            for (int k = 0; k < 16; k++)
                if ((k & 4) && !(k & 2)) appRX(v[k], v[k | 2], c, s);
        }
        {
            float c = cs[base + 41], s = sn[base + 41];
            #pragma unroll
            for (int k = 0; k < 16; k++)
                if ((k & 2) && !(k & 1)) appRX(v[k], v[k | 1], c, s);
        }
        // U7 + F6 (ctrl wire6=k0, per-k select): shfl m=16
        {
            float4 p  = gL[14], q  = gL[15];   // U7 pair
            float4 pw = gL[16], qw = gL[17];   // W7 pair
            int own = (t >> 4) & 1;
            float2 Am = own ? make_float2(p.z,  p.w)  : make_float2(p.x,  p.y);
            float2 Bm = own ? make_float2(q.z,  q.w)  : make_float2(q.x,  q.y);
            float2 Aw = own ? make_float2(pw.z, pw.w) : make_float2(pw.x, pw.y);
            float2 Bw = own ? make_float2(qw.z, qw.w) : make_float2(qw.x, qw.y);
            #pragma unroll
            for (int k = 0; k < 16; k++) {
                float px = __shfl_xor_sync(FM, v[k].x, 16);
                float py = __shfl_xor_sync(FM, v[k].y, 16);
                float2 pp = make_float2(px, py);
                v[k] = (k & 1) ? axpb(Aw, v[k], Bw, pp) : axpb(Am, v[k], Bm, pp);
            }
        }
        // U8..U11 + F7..F10: shfl m=8,4,2,1 ; fused variant if t&(m<<1)
        #pragma unroll
        for (int w = 8; w < 12; w++) {
            const int m = 1 << (11 - w);
            int slot = (t & (m << 1)) ? (13 + w - 8) : (9 + w - 8);
            float4 p = gL[2 * slot], q = gL[2 * slot + 1];
            int own = (t & m) ? 1 : 0;
            float2 A = own ? make_float2(p.z, p.w) : make_float2(p.x, p.y);
            float2 B = own ? make_float2(q.z, q.w) : make_float2(q.x, q.y);
            #pragma unroll
            for (int k = 0; k < 16; k++) {
                float px = __shfl_xor_sync(FM, v[k].x, m);
                float py = __shfl_xor_sync(FM, v[k].y, m);
                v[k] = axpb(A, v[k], B, make_float2(px, py));
            }
        }
        // F11: ctrl wire11=t0, tgt wire0=k3 (local)
        {
            float c = cs[base + 47], s = sn[base + 47];
            if (t & 1) {
                #pragma unroll
                for (int k = 0; k < 8; k++) appRX(v[k], v[k | 8], c, s);
            }
        }
        // B11..B8: shfl CRX, tgt m=2,4,8,16 ; ctrl = m>>1
        #pragma unroll
        for (int i = 11; i >= 8; i--) {
            const int m = 1 << (12 - i);
            float c = cs[base + 48 + (11 - i)], s = sn[base + 48 + (11 - i)];
            int cond = t & (m >> 1);
            #pragma unroll
            for (int k = 0; k < 16; k++) {
                float px = __shfl_xor_sync(FM, v[k].x, m);
                float py = __shfl_xor_sync(FM, v[k].y, m);
                if (cond) v[k] = rx1(v[k], make_float2(px, py), c, s);
            }
        }
        // B7: ctrl wire7=t4 (t&16), tgt wire6=k0 (local)
        {
            float c = cs[base + 52], s = sn[base + 52];
            if (t & 16) {
                #pragma unroll
                for (int k = 0; k < 16; k += 2) appRX(v[k], v[k | 1], c, s);
            }
        }
        // B6: ctrl k0 -> tgt k1 ; B5: ctrl k1 -> tgt k2 (local)
        {
            float c = cs[base + 53], s = sn[base + 53];
            #pragma unroll
            for (int k = 0; k < 16; k++)
                if ((k & 1) && !(k & 2)) appRX(v[k], v[k | 2], c, s);
        }
        {
            float c = cs[base + 54], s = sn[base + 54];
            #pragma unroll
            for (int k = 0; k < 16; k++)
                if ((k & 2) && !(k & 4)) appRX(v[k], v[k | 4], c, s);
        }

        // ========== Transpose M1 -> M0 (bufB) ==========
        #pragma unroll
        for (int k = 0; k < 16; k++)
            bufB[tbase | ((k & 8) << 8) | ((k & 7) << 5)] = v[k];
        __syncthreads();
        #pragma unroll
        for (int k = 0; k < 16; k++) v[k] = bufB[(k << 8) | t];

        // ========== Phase 3 (M0): B4..B0 ==========
        // B4: ctrl wire4=t7 (t&128), tgt wire3=k0
        {
            float c = cs[base + 55], s = sn[base + 55];
            if (t & 128) {
                #pragma unroll
                for (int k = 0; k < 16; k += 2) appRX(v[k], v[k | 1], c, s);
            }
        }
        // B3,B2,B1: ctrl k(j) -> tgt k(j+1)
        #pragma unroll
        for (int j = 0; j < 3; j++) {
            float c = cs[base + 56 + j], s = sn[base + 56 + j];
            int cb = 1 << j, tb = 2 << j;
            #pragma unroll
            for (int k = 0; k < 16; k++)
                if ((k & cb) && !(k & tb)) appRX(v[k], v[k | tb], c, s);
        }
        // B0: ctrl wire0=k3 (k>=8), tgt wire11=t0 (shfl m=1)
        {
            float c = cs[base + 59], s = sn[base + 59];
            #pragma unroll
            for (int k = 8; k < 16; k++) {
                float px = __shfl_xor_sync(FM, v[k].x, 1);
                float py = __shfl_xor_sync(FM, v[k].y, 1);
                v[k] = rx1(v[k], make_float2(px, py), c, s);
            }
        }
    }

    // ================= expectations (M0) =================
    #pragma unroll
    for (int k = 0; k < 16; k++) bufA[(k << 8) | t] = v[k];
    __syncthreads();

    float nv[16], S = 0.0f;
    #pragma unroll
    for (int k = 0; k < 16; k++) {
        nv[k] = fmaf(v[k].x, v[k].x, v[k].y * v[k].y);
        S += nv[k];
    }

    // wires 0-3: k-bit pairs (register-local)
    #pragma unroll
    for (int w = 0; w < 4; w++) {
        int kb = 1 << (3 - w);
        float rr = 0.f, ri = 0.f, rz = 0.f;
        #pragma unroll
        for (int k = 0; k < 16; k++) {
            if (!(k & kb)) {
                float2 a = v[k], c = v[k | kb];
                rr = fmaf(a.x, c.x, fmaf( a.y, c.y, rr));
                ri = fmaf(a.x, c.y, fmaf(-a.y, c.x, ri));
            }
            rz += (k & kb) ? -nv[k] : nv[k];
        }
        #pragma unroll
        for (int off = 16; off; off >>= 1) {
            rr += __shfl_down_sync(FM, rr, off);
            ri += __shfl_down_sync(FM, ri, off);
            rz += __shfl_down_sync(FM, rz, off);
        }
        if (lane == 0) {
            rbuf[w * 8 + warp]       = rr;
            rbuf[96 + w * 8 + warp]  = ri;
            rbuf[192 + w * 8 + warp] = rz;
        }
    }

    // wires 4-6: warp-bit pairs (partner from bufA; own-bit==0 threads only)
    #pragma unroll
    for (int w = 4; w < 7; w++) {
        int pb = 11 - w;
        int own = (t >> pb) & 1;
        float rr = 0.f, ri = 0.f;
        if (!own) {
            int pt = t | (1 << pb);
            #pragma unroll
            for (int k = 0; k < 16; k++) {
                float2 c = bufA[(k << 8) | pt];
                rr = fmaf(v[k].x, c.x, fmaf( v[k].y, c.y, rr));
                ri = fmaf(v[k].x, c.y, fmaf(-v[k].y, c.x, ri));
            }
        }
        float rz = own ? -S : S;
        #pragma unroll
        for (int off = 16; off; off >>= 1) {
            rr += __shfl_down_sync(FM, rr, off);
            ri += __shfl_down_sync(FM, ri, off);
            rz += __shfl_down_sync(FM, rz, off);
        }
        if (lane == 0) {
            rbuf[w * 8 + warp]       = rr;
            rbuf[96 + w * 8 + warp]  = ri;
            rbuf[192 + w * 8 + warp] = rz;
        }
    }

    // wires 7-11: lane-bit pairs (shfl partner)
    #pragma unroll
    for (int w = 7; w < 12; w++) {
        int m = 1 << (11 - w);
        int own = (t & m) ? 1 : 0;
        float rr = 0.f, ri = 0.f;
        #pragma unroll
        for (int k = 0; k < 16; k++) {
            float px = __shfl_xor_sync(FM, v[k].x, m);
            float py = __shfl_xor_sync(FM, v[k].y, m);
            if (!own) {
                rr = fmaf(v[k].x, px, fmaf( v[k].y, py, rr));
                ri = fmaf(v[k].x, py, fmaf(-v[k].y, px, ri));
            }
        }
        float rz = own ? -S : S;
        #pragma unroll
        for (int off = 16; off; off >>= 1) {
            rr += __shfl_down_sync(FM, rr, off);
            ri += __shfl_down_sync(FM, ri, off);
            rz += __shfl_down_sync(FM, rz, off);
        }
        if (lane == 0) {
            rbuf[w * 8 + warp]       = rr;
            rbuf[96 + w * 8 + warp]  = ri;
            rbuf[192 + w * 8 + warp] = rz;
        }
    }

    __syncthreads();
    if (t < 36) {
        float a = 0.f;
        #pragma unroll
        for (int q = 0; q < 8; q++) a += rbuf[t * 8 + q];
        out[b * 36 + t] = (t < 24) ? 2.0f * a : a;
    }
}

extern "C" void kernel_launch(void* const* d_in, const int* in_sizes, int n_in,
                              void* d_out, int out_size) {
    const float* params = (const float*)d_in[0];   // (B, 240) float32
    const float* inputs = (const float*)d_in[1];   // (B, 12)  float32
    float* out = (float*)d_out;                    // (B, 36)  float32
    int B = in_sizes[0] / NPARAM;
    static bool attr_set = false;
    if (!attr_set) {
        cudaFuncSetAttribute(qfe_kernel,
                             cudaFuncAttributeMaxDynamicSharedMemorySize,
                             SMEM_BYTES);
        attr_set = true;
    }
    qfe_kernel<<<B, TPB, SMEM_BYTES>>>(params, inputs, out);
}

// round 16
// speedup vs baseline: 1.4136x; 1.0040x over previous
#include <cuda_runtime.h>

#define NQ     12
#define TPB    256
#define NPARAM 240          // 12 * 4 * 5
#define NLAYER 4
#define FM     0xffffffffu

// 64KB state bufs + 1088B SU(2) table + trig/reduce floats
#define SMEM_BYTES 69792

// new = A*v + B*p  (complex)
__device__ __forceinline__ float2 axpb(float2 A, float2 v, float2 B, float2 p) {
    return make_float2(
        fmaf(A.x, v.x, fmaf(-A.y, v.y, fmaf(B.x, p.x, -B.y * p.y))),
        fmaf(A.x, v.y, fmaf( A.y, v.x, fmaf(B.x, p.y,  B.y * p.x))));
}
// SU(2) gate on a register pair: M = [[a, -b*],[b, a*]]
__device__ __forceinline__ void su2_pair(float2 &s0, float2 &s1, float2 a, float2 b) {
    float n0x = fmaf(a.x, s0.x, fmaf(-a.y, s0.y, fmaf(-b.x, s1.x, -b.y * s1.y)));
    float n0y = fmaf(a.x, s0.y, fmaf( a.y, s0.x, fmaf(-b.x, s1.y,  b.y * s1.x)));
    float n1x = fmaf(b.x, s0.x, fmaf(-b.y, s0.y, fmaf( a.x, s1.x,  a.y * s1.y)));
    float n1y = fmaf(b.x, s0.y, fmaf( b.y, s0.x, fmaf( a.x, s1.y, -a.y * s1.x)));
    s0 = make_float2(n0x, n0y);
    s1 = make_float2(n1x, n1y);
}
// one-sided RX: n = c*v - i s*p
__device__ __forceinline__ float2 rx1(float2 v, float2 p, float c, float s) {
    return make_float2(fmaf(c, v.x, s * p.y), fmaf(c, v.y, -s * p.x));
}
// RX on a register pair
__device__ __forceinline__ void appRX(float2 &a, float2 &b, float c, float s) {
    float2 na = rx1(a, b, c, s);
    float2 nb = rx1(b, a, c, s);
    a = na; b = nb;
}
__device__ __forceinline__ float2 cmulf(float2 a, float2 b) {
    return make_float2(fmaf(a.x, b.x, -a.y * b.y), fmaf(a.x, b.y, a.y * b.x));
}
// M = Rz * Ry * Rx  (gates applied in order Rx, Ry, Rz); SU(2): return a=M00, b=M10
__device__ __forceinline__ void build_u(const float* cs, const float* sn, int pi,
        float2 &M00, float2 &M01, float2 &M10, float2 &M11) {
    float cx = cs[pi],     sx = sn[pi];
    float cy = cs[pi + 1], sy = sn[pi + 1];
    float cz = cs[pi + 2], sz = sn[pi + 2];
    float2 A00 = make_float2( cy * cx,  sy * sx);
    float2 A01 = make_float2(-sy * cx, -cy * sx);
    float2 A10 = make_float2( sy * cx, -cy * sx);
    float2 A11 = make_float2( cy * cx, -sy * sx);
    float2 ez  = make_float2(cz, -sz), ezc = make_float2(cz, sz);
    M00 = cmulf(ez,  A00); M01 = cmulf(ez,  A01);
    M10 = cmulf(ezc, A10); M11 = cmulf(ezc, A11);
}
// M <- RX(c,s) * M   (RX applied after M)
__device__ __forceinline__ void fuse_rx(float c, float s,
        float2 &M00, float2 &M01, float2 &M10, float2 &M11) {
    float2 W00 = make_float2(fmaf(c, M00.x,  s * M10.y), fmaf(c, M00.y, -s * M10.x));
    float2 W01 = make_float2(fmaf(c, M01.x,  s * M11.y), fmaf(c, M01.y, -s * M11.x));
    float2 W10 = make_float2(fmaf(c, M10.x,  s * M00.y), fmaf(c, M10.y, -s * M00.x));
    float2 W11 = make_float2(fmaf(c, M11.x,  s * M01.y), fmaf(c, M11.y, -s * M01.x));
    M00 = W00; M01 = W01; M10 = W10; M11 = W11;
}

// SU(2) table: 17 slots per layer, ONE float4 per slot = (a.x, a.y, b.x, b.y).
//  slots 0-3 : U0..U3 ; 4-6 : U4..U6 ; 7 : U7 ; 8 : W7=F6*U7
//  9-12: U8..U11 ; 13-16: W8..W11 (F_{w-1} fused)
// Own-bit select (pair passes): A=(a.x, own?-a.y:a.y), B=(own?b.x:-b.x, b.y)
//
// Mappings (idx bit 11-w <-> wire w physically):
//  M0: i = (k<<8)|t.  wires 0-3 <-> k3..k0 ; 4-6 <-> t7..t5 ; 7-11 <-> t4..t0
//  M1: i11=k3, i10..i8=t7..t5, i7..i5=k2..k0, i4..i0=t4..t0
__global__ void __launch_bounds__(TPB, 3) qfe_kernel(
    const float* __restrict__ params,   // (B, 240)
    const float* __restrict__ inputs,   // (B, 12)
    float* __restrict__ out)            // (B, 36)
{
    extern __shared__ float smem_raw[];
    float2* bufA = (float2*)smem_raw;            // 4096 float2 = 32 KB
    float2* bufB = bufA + 4096;                  // 32 KB
    float4* gmat = (float4*)(bufB + 4096);       // 68 float4 = 1088 B
    float*  cs   = (float*)(gmat + 68);          // 240
    float*  sn   = cs + NPARAM;                  // 240
    float*  eic  = sn + NPARAM;                  // 12
    float*  eis  = eic + NQ;                     // 12
    float*  rbuf = eis + NQ;                     // 288

    const int b = blockIdx.x;
    const int t = threadIdx.x;
    const int lane = t & 31, warp = t >> 5;
    // M1 address base: bits 10-8 <- t7..t5, bits 4-0 <- t4..t0
    const int tbase = ((t & 0xE0) << 3) | (t & 31);

    // ---- stage all trig once per block
    if (t < NPARAM) {
        float h = 0.5f * params[b * NPARAM + t];
        sincosf(h, &sn[t], &cs[t]);
    } else if (t < NPARAM + NQ) {
        int i = t - NPARAM;
        float h = 0.5f * inputs[b * NQ + i];
        sincosf(h, &eis[i], &eic[i]);
    }
    __syncthreads();

    // ---- build all SU(2) gate coefficients once per block (68 builder threads)
    if (t < 68) {
        int L = t / 17, slot = t - L * 17;
        int base = 60 * L;
        float2 M00, M01, M10, M11;
        if (slot < 4) {          // U0..U3
            build_u(cs, sn, base + 3 * slot, M00, M01, M10, M11);
        } else if (slot < 7) {   // U4..U6
            build_u(cs, sn, base + 12 + 3 * (slot - 4), M00, M01, M10, M11);
        } else if (slot == 7) {  // U7
            build_u(cs, sn, base + 21, M00, M01, M10, M11);
        } else if (slot == 8) {  // W7 = F6 * U7
            build_u(cs, sn, base + 21, M00, M01, M10, M11);
            fuse_rx(cs[base + 42], sn[base + 42], M00, M01, M10, M11);
        } else if (slot < 13) {  // U8..U11
            int w = slot - 9 + 8;
            build_u(cs, sn, base + 3 * w, M00, M01, M10, M11);
        } else {                 // W8..W11 = F_{w-1} * U_w
            int w = slot - 13 + 8;
            build_u(cs, sn, base + 3 * w, M00, M01, M10, M11);
            fuse_rx(cs[base + 36 + w - 1], sn[base + 36 + w - 1], M00, M01, M10, M11);
        }
        gmat[L * 17 + slot] = make_float4(M00.x, M00.y, M10.x, M10.y);
    }

    // ---- init (M0): RY(input) product state (overlap with builder, sync after)
    float2 v[16];
    {
        float tp = 1.0f;
        #pragma unroll
        for (int w = 4; w < 12; w++)
            tp *= ((t >> (11 - w)) & 1) ? eis[w] : eic[w];
        #pragma unroll
        for (int k = 0; k < 16; k++) {
            float a = tp;
            #pragma unroll
            for (int w = 0; w < 4; w++)
                a *= ((k >> (3 - w)) & 1) ? eis[w] : eic[w];
            v[k] = make_float2(a, 0.0f);
        }
    }
    __syncthreads();

    #pragma unroll 1
    for (int L = 0; L < NLAYER; L++) {
        const int base = 60 * L;
        const float4* gL = gmat + L * 17;

        // ========== Phase 1 (M0): U0..U3, F0..F2 — register-local ==========
        #pragma unroll
        for (int w = 0; w < 4; w++) {
            float4 g = gL[w];
            float2 ga = make_float2(g.x, g.y), gb = make_float2(g.z, g.w);
            int kb = 8 >> w;
            #pragma unroll
            for (int k = 0; k < 16; k++) if (!(k & kb))
                su2_pair(v[k], v[k | kb], ga, gb);
        }
        #pragma unroll
        for (int i = 0; i < 3; i++) {    // F0,F1,F2: ctrl k(3-i) -> tgt k(2-i)
            float c = cs[base + 36 + i], s = sn[base + 36 + i];
            int cb = 8 >> i, tb = 4 >> i;
            #pragma unroll
            for (int k = 0; k < 16; k++)
                if ((k & cb) && !(k & tb)) appRX(v[k], v[k | tb], c, s);
        }

        // ========== Transpose M0 -> M1 (bufA) ==========
        #pragma unroll
        for (int k = 0; k < 16; k++) bufA[(k << 8) | t] = v[k];
        __syncthreads();
        #pragma unroll
        for (int k = 0; k < 16; k++)
            v[k] = bufA[tbase | ((k & 8) << 8) | ((k & 7) << 5)];

        // ========== Phase 2 (M1) ==========
        // U4,U5,U6: k-local (k2,k1,k0)
        #pragma unroll
        for (int j = 0; j < 3; j++) {
            float4 g = gL[4 + j];
            float2 ga = make_float2(g.x, g.y), gb = make_float2(g.z, g.w);
            int kb = 4 >> j;
            #pragma unroll
            for (int k = 0; k < 16; k++) if (!(k & kb))
                su2_pair(v[k], v[k | kb], ga, gb);
        }
        // F3: ctrl wire3=t5 (t&32), tgt wire4=k2
        {
            float c = cs[base + 39], s = sn[base + 39];
            if (t & 32) {
                #pragma unroll
                for (int k = 0; k < 16; k++)
                    if (!(k & 4)) appRX(v[k], v[k | 4], c, s);
            }
        }
        // F4: ctrl k2 -> tgt k1 ; F5: ctrl k1 -> tgt k0
        {
            float c = cs[base + 40], s = sn[base + 40];
            #pragma unroll
            for (int k = 0; k < 16; k++)
                if ((k & 4) && !(k & 2)) appRX(v[k], v[k | 2], c, s);
        }
        {
            float c = cs[base + 41], s = sn[base + 41];
            #pragma unroll
            for (int k = 0; k < 16; k++)
                if ((k & 2) && !(k & 1)) appRX(v[k], v[k | 1], c, s);
        }
        // U7 + F6 (ctrl wire6=k0, per-k select): shfl m=16
        {
            float4 gm = gL[7], gw = gL[8];
            int own = (t >> 4) & 1;
            float2 Am = make_float2(gm.x, own ? -gm.y : gm.y);
            float2 Bm = make_float2(own ? gm.z : -gm.z, gm.w);
            float2 Aw = make_float2(gw.x, own ? -gw.y : gw.y);
            float2 Bw = make_float2(own ? gw.z : -gw.z, gw.w);
            #pragma unroll
            for (int k = 0; k < 16; k++) {
                float px = __shfl_xor_sync(FM, v[k].x, 16);
                float py = __shfl_xor_sync(FM, v[k].y, 16);
                float2 pp = make_float2(px, py);
                v[k] = (k & 1) ? axpb(Aw, v[k], Bw, pp) : axpb(Am, v[k], Bm, pp);
            }
        }
        // U8..U11 + F7..F10: shfl m=8,4,2,1 ; fused variant if t&(m<<1)
        #pragma unroll
        for (int w = 8; w < 12; w++) {
            const int m = 1 << (11 - w);
            int slot = (t & (m << 1)) ? (5 + w) : (1 + w);   // 13+(w-8) : 9+(w-8)
            float4 g = gL[slot];
            int own = (t & m) ? 1 : 0;
            float2 A = make_float2(g.x, own ? -g.y : g.y);
            float2 B = make_float2(own ? g.z : -g.z, g.w);
            #pragma unroll
            for (int k = 0; k < 16; k++) {
                float px = __shfl_xor_sync(FM, v[k].x, m);
                float py = __shfl_xor_sync(FM, v[k].y, m);
                v[k] = axpb(A, v[k], B, make_float2(px, py));
            }
        }
        // F11: ctrl wire11=t0, tgt wire0=k3 (local)
        {
            float c = cs[base + 47], s = sn[base + 47];
            if (t & 1) {
                #pragma unroll
                for (int k = 0; k < 8; k++) appRX(v[k], v[k | 8], c, s);
            }
        }
        // B11..B8: shfl CRX, tgt m=2,4,8,16 ; ctrl = m>>1
        #pragma unroll
        for (int i = 11; i >= 8; i--) {
            const int m = 1 << (12 - i);
            float c = cs[base + 48 + (11 - i)], s = sn[base + 48 + (11 - i)];
            int cond = t & (m >> 1);
            #pragma unroll
            for (int k = 0; k < 16; k++) {
                float px = __shfl_xor_sync(FM, v[k].x, m);
                float py = __shfl_xor_sync(FM, v[k].y, m);
                if (cond) v[k] = rx1(v[k], make_float2(px, py), c, s);
            }
        }
        // B7: ctrl wire7=t4 (t&16), tgt wire6=k0 (local)
        {
            float c = cs[base + 52], s = sn[base + 52];
            if (t & 16) {
                #pragma unroll
                for (int k = 0; k < 16; k += 2) appRX(v[k], v[k | 1], c, s);
            }
        }
        // B6: ctrl k0 -> tgt k1 ; B5: ctrl k1 -> tgt k2 (local)
        {
            float c = cs[base + 53], s = sn[base + 53];
            #pragma unroll
            for (int k = 0; k < 16; k++)
                if ((k & 1) && !(k & 2)) appRX(v[k], v[k | 2], c, s);
        }
        {
            float c = cs[base + 54], s = sn[base + 54];
            #pragma unroll
            for (int k = 0; k < 16; k++)
                if ((k & 2) && !(k & 4)) appRX(v[k], v[k | 4], c, s);
        }

        // ========== Transpose M1 -> M0 (bufB) ==========
        #pragma unroll
        for (int k = 0; k < 16; k++)
            bufB[tbase | ((k & 8) << 8) | ((k & 7) << 5)] = v[k];
        __syncthreads();
        #pragma unroll
        for (int k = 0; k < 16; k++) v[k] = bufB[(k << 8) | t];

        // ========== Phase 3 (M0): B4..B0 ==========
        // B4: ctrl wire4=t7 (t&128), tgt wire3=k0
        {
            float c = cs[base + 55], s = sn[base + 55];
            if (t & 128) {
                #pragma unroll
                for (int k = 0; k < 16; k += 2) appRX(v[k], v[k | 1], c, s);
            }
        }
        // B3,B2,B1: ctrl k(j) -> tgt k(j+1)
        #pragma unroll
        for (int j = 0; j < 3; j++) {
            float c = cs[base + 56 + j], s = sn[base + 56 + j];
            int cb = 1 << j, tb = 2 << j;
            #pragma unroll
            for (int k = 0; k < 16; k++)
                if ((k & cb) && !(k & tb)) appRX(v[k], v[k | tb], c, s);
        }
        // B0: ctrl wire0=k3 (k>=8), tgt wire11=t0 (shfl m=1)
        {
            float c = cs[base + 59], s = sn[base + 59];
            #pragma unroll
            for (int k = 8; k < 16; k++) {
                float px = __shfl_xor_sync(FM, v[k].x, 1);
                float py = __shfl_xor_sync(FM, v[k].y, 1);
                v[k] = rx1(v[k], make_float2(px, py), c, s);
            }
        }
    }

    // ================= expectations (M0) =================
    #pragma unroll
    for (int k = 0; k < 16; k++) bufA[(k << 8) | t] = v[k];
    __syncthreads();

    float nv[16], S = 0.0f;
    #pragma unroll
    for (int k = 0; k < 16; k++) {
        nv[k] = fmaf(v[k].x, v[k].x, v[k].y * v[k].y);
        S += nv[k];
    }

    // wires 0-3: k-bit pairs (register-local)
    #pragma unroll
    for (int w = 0; w < 4; w++) {
        int kb = 1 << (3 - w);
        float rr = 0.f, ri = 0.f, rz = 0.f;
        #pragma unroll
        for (int k = 0; k < 16; k++) {
            if (!(k & kb)) {
                float2 a = v[k], c = v[k | kb];
                rr = fmaf(a.x, c.x, fmaf( a.y, c.y, rr));
                ri = fmaf(a.x, c.y, fmaf(-a.y, c.x, ri));
            }
            rz += (k & kb) ? -nv[k] : nv[k];
        }
        #pragma unroll
        for (int off = 16; off; off >>= 1) {
            rr += __shfl_down_sync(FM, rr, off);
            ri += __shfl_down_sync(FM, ri, off);
            rz += __shfl_down_sync(FM, rz, off);
        }
        if (lane == 0) {
            rbuf[w * 8 + warp]       = rr;
            rbuf[96 + w * 8 + warp]  = ri;
            rbuf[192 + w * 8 + warp] = rz;
        }
    }

    // wires 4-6: warp-bit pairs (partner from bufA; own-bit==0 threads only)
    #pragma unroll
    for (int w = 4; w < 7; w++) {
        int pb = 11 - w;
        int own = (t >> pb) & 1;
        float rr = 0.f, ri = 0.f;
        if (!own) {
            int pt = t | (1 << pb);
            #pragma unroll
            for (int k = 0; k < 16; k++) {
                float2 c = bufA[(k << 8) | pt];
                rr = fmaf(v[k].x, c.x, fmaf( v[k].y, c.y, rr));
                ri = fmaf(v[k].x, c.y, fmaf(-v[k].y, c.x, ri));
            }
        }
        float rz = own ? -S : S;
        #pragma unroll
        for (int off = 16; off; off >>= 1) {
            rr += __shfl_down_sync(FM, rr, off);
            ri += __shfl_down_sync(FM, ri, off);
            rz += __shfl_down_sync(FM, rz, off);
        }
        if (lane == 0) {
            rbuf[w * 8 + warp]       = rr;
            rbuf[96 + w * 8 + warp]  = ri;
            rbuf[192 + w * 8 + warp] = rz;
        }
    }

    // wires 7-11: lane-bit pairs (shfl partner)
    #pragma unroll
    for (int w = 7; w < 12; w++) {
        int m = 1 << (11 - w);
        int own = (t & m) ? 1 : 0;
        float rr = 0.f, ri = 0.f;
        #pragma unroll
        for (int k = 0; k < 16; k++) {
            float px = __shfl_xor_sync(FM, v[k].x, m);
            float py = __shfl_xor_sync(FM, v[k].y, m);
            if (!own) {
                rr = fmaf(v[k].x, px, fmaf( v[k].y, py, rr));
                ri = fmaf(v[k].x, py, fmaf(-v[k].y, px, ri));
            }
        }
        float rz = own ? -S : S;
        #pragma unroll
        for (int off = 16; off; off >>= 1) {
            rr += __shfl_down_sync(FM, rr, off);
            ri += __shfl_down_sync(FM, ri, off);
            rz += __shfl_down_sync(FM, rz, off);
        }
        if (lane == 0) {
            rbuf[w * 8 + warp]       = rr;
            rbuf[96 + w * 8 + warp]  = ri;
            rbuf[192 + w * 8 + warp] = rz;
        }
    }

    __syncthreads();
    if (t < 36) {
        float a = 0.f;
        #pragma unroll
        for (int q = 0; q < 8; q++) a += rbuf[t * 8 + q];
        out[b * 36 + t] = (t < 24) ? 2.0f * a : a;
    }
}

extern "C" void kernel_launch(void* const* d_in, const int* in_sizes, int n_in,
                              void* d_out, int out_size) {
    const float* params = (const float*)d_in[0];   // (B, 240) float32
    const float* inputs = (const float*)d_in[1];   // (B, 12)  float32
    float* out = (float*)d_out;                    // (B, 36)  float32
    int B = in_sizes[0] / NPARAM;
    static bool attr_set = false;
    if (!attr_set) {
        cudaFuncSetAttribute(qfe_kernel,
                             cudaFuncAttributeMaxDynamicSharedMemorySize,
                             SMEM_BYTES);
        attr_set = true;
    }
    qfe_kernel<<<B, TPB, SMEM_BYTES>>>(params, inputs, out);
}